// round 4
// baseline (speedup 1.0000x reference)
#include <cuda_runtime.h>
#include <math.h>

// ---------------------------------------------------------------------------
// NeuralSDE (Euler-Heun / Stratonovich) persistent kernel, round 3.
// 128 CTAs x 512 threads, 4 samples per CTA, 6 barriers/step.
// Diffusion final layer: sample-pair packed f32x2 accumulators, float2 weight
// loads (no splat-unpack), unroll 8. Drift moved into phase D (k-split pairs).
// ---------------------------------------------------------------------------

#define kH     64
#define kNoise 16
#define kData  8
#define kW     128
#define kB     512
#define kT     1025
#define kSteps 1024
#define BS     4
#define NCTA   128
#define NTHR   512
#define kCO    1024

using u64 = unsigned long long;

// Transposed big weights (k-major). element (k,j) at float index k*1024+j.
__device__ u64   g_cW2t[kW * kCO / 2];
__device__ float g_vW2t[kW * kH];        // (k,h) at k*64 + h

struct Smem {
  float vW0t[65][kW];
  float cW0t[65][kW];
  float vW1t[kW][kW];
  float cW1t[kW][kW];
  float vb0[kW], vb1[kW], cb0[kW], cb1[kW];
  float vb2[kH], vscl[kH];
  float cb2[kCO];
  float cscl[kCO];
  float roWt[kH][kData];
  float rob[kData];
  float4 ys4[kH];
  float4 g04[kH];
  float4 f04[kH];
  float4 yp4[kH];
  float4 h0v4[kW];
  float4 h0c4[kW];
  float4 h1v4[kW];
  float4 h1c4[kW];
  float  dws[BS][kNoise];
};

__global__ void transpose_kernel(const float* __restrict__ cW2,
                                 const float* __restrict__ vW2) {
  int idx = blockIdx.x * blockDim.x + threadIdx.x;
  int stride = gridDim.x * blockDim.x;
  float* ct = reinterpret_cast<float*>(g_cW2t);
  for (int i = idx; i < kW * kCO; i += stride) {
    int k = i >> 10, j = i & (kCO - 1);
    ct[i] = cW2[j * kW + k];            // cW2 is (1024, 128) row-major
  }
  for (int i = idx; i < kW * kH; i += stride) {
    int k = i >> 6, h = i & (kH - 1);
    g_vW2t[i] = vW2[h * kW + k];        // vW2 is (64, 128) row-major
  }
}

__device__ __forceinline__ u64 pack2(float lo, float hi) {
  u64 r; asm("mov.b64 %0,{%1,%2};" : "=l"(r) : "f"(lo), "f"(hi)); return r;
}
__device__ __forceinline__ void unpack2(u64 v, float& lo, float& hi) {
  asm("mov.b64 {%0,%1},%2;" : "=f"(lo), "=f"(hi) : "l"(v));
}
__device__ __forceinline__ u64 fma2(u64 a, u64 b, u64 c) {
  u64 d; asm("fma.rn.f32x2 %0,%1,%2,%3;" : "=l"(d) : "l"(a), "l"(b), "l"(c));
  return d;
}

__device__ __forceinline__ float lipswish(float x) {
  return 0.909f * x * (1.0f / (1.0f + expf(-x)));
}

// Diffusion final layer core. Writes p0..p3 (per-sample contraction partials
// reduced over this thread's 2 cols); caller reduces over 8 lanes.
__device__ __forceinline__ void diff_core(const Smem& s, int tid, int j0,
                                          const float4* __restrict__ h1,
                                          float& p0, float& p1, float& p2, float& p3) {
  const float c0 = s.cb2[j0], c1 = s.cb2[j0 + 1];
  u64 A0 = pack2(c0, c0), A1 = A0;        // col j0,   samples (0,1) / (2,3)
  u64 B0 = pack2(c1, c1), B1 = B0;        // col j0+1
  const float2* wrow = reinterpret_cast<const float2*>(g_cW2t) + tid;
#pragma unroll 8
  for (int k = 0; k < kW; ++k) {
    float2 w = __ldg(&wrow[(size_t)k * (kCO / 2)]);
    ulonglong2 xv = *reinterpret_cast<const ulonglong2*>(&h1[k]);
    u64 w0 = pack2(w.x, w.x);
    u64 w1 = pack2(w.y, w.y);
    A0 = fma2(w0, xv.x, A0); A1 = fma2(w0, xv.y, A1);
    B0 = fma2(w1, xv.x, B0); B1 = fma2(w1, xv.y, B1);
  }
  float a0, a1, a2, a3, b0, b1, b2, b3;
  unpack2(A0, a0, a1); unpack2(A1, a2, a3);
  unpack2(B0, b0, b1); unpack2(B1, b2, b3);
  const float cs0 = s.cscl[j0], cs1 = s.cscl[j0 + 1];
  const int n0 = j0 & (kNoise - 1);
  float2 d0 = *reinterpret_cast<const float2*>(&s.dws[0][n0]);
  float2 d1 = *reinterpret_cast<const float2*>(&s.dws[1][n0]);
  float2 d2 = *reinterpret_cast<const float2*>(&s.dws[2][n0]);
  float2 d3 = *reinterpret_cast<const float2*>(&s.dws[3][n0]);
  p0 = tanhf(a0) * cs0 * d0.x + tanhf(b0) * cs1 * d0.y;
  p1 = tanhf(a1) * cs0 * d1.x + tanhf(b1) * cs1 * d1.y;
  p2 = tanhf(a2) * cs0 * d2.x + tanhf(b2) * cs1 * d2.y;
  p3 = tanhf(a3) * cs0 * d3.x + tanhf(b3) * cs1 * d3.y;
  p0 += __shfl_xor_sync(~0u, p0, 1); p0 += __shfl_xor_sync(~0u, p0, 2); p0 += __shfl_xor_sync(~0u, p0, 4);
  p1 += __shfl_xor_sync(~0u, p1, 1); p1 += __shfl_xor_sync(~0u, p1, 2); p1 += __shfl_xor_sync(~0u, p1, 4);
  p2 += __shfl_xor_sync(~0u, p2, 1); p2 += __shfl_xor_sync(~0u, p2, 2); p2 += __shfl_xor_sync(~0u, p2, 4);
  p3 += __shfl_xor_sync(~0u, p3, 1); p3 += __shfl_xor_sync(~0u, p3, 2); p3 += __shfl_xor_sync(~0u, p3, 4);
}

__global__ __launch_bounds__(NTHR, 1) void sde_kernel(
    const float* __restrict__ ts, const float* __restrict__ z0,
    const float* __restrict__ dW,
    const float* __restrict__ iW0, const float* __restrict__ ib0,
    const float* __restrict__ iW1, const float* __restrict__ ib1,
    const float* __restrict__ iW2, const float* __restrict__ ib2,
    const float* __restrict__ vW0, const float* __restrict__ vb0,
    const float* __restrict__ vW1, const float* __restrict__ vb1,
    const float* __restrict__ vb2, const float* __restrict__ vscale,
    const float* __restrict__ cW0, const float* __restrict__ cb0,
    const float* __restrict__ cW1, const float* __restrict__ cb1,
    const float* __restrict__ cb2, const float* __restrict__ cscale,
    const float* __restrict__ roW, const float* __restrict__ rob,
    float* __restrict__ out) {
  extern __shared__ char smem_raw[];
  Smem& s = *reinterpret_cast<Smem*>(smem_raw);
  const int tid = threadIdx.x;
  const int bbase = blockIdx.x * BS;

  // ---- load small weights transposed into smem ----
  for (int i = tid; i < 65 * kW; i += NTHR) {
    int k = i >> 7, j = i & 127;
    s.vW0t[k][j] = vW0[j * 65 + k];
    s.cW0t[k][j] = cW0[j * 65 + k];
  }
  for (int i = tid; i < kW * kW; i += NTHR) {
    int k = i >> 7, j = i & 127;
    s.vW1t[k][j] = vW1[j * kW + k];
    s.cW1t[k][j] = cW1[j * kW + k];
  }
  for (int i = tid; i < kW; i += NTHR) {
    s.vb0[i] = vb0[i]; s.vb1[i] = vb1[i];
    s.cb0[i] = cb0[i]; s.cb1[i] = cb1[i];
  }
  for (int i = tid; i < kH; i += NTHR) { s.vb2[i] = vb2[i]; s.vscl[i] = vscale[i]; }
  for (int i = tid; i < kCO; i += NTHR) { s.cb2[i] = cb2[i]; s.cscl[i] = cscale[i]; }
  for (int i = tid; i < kH * kData; i += NTHR) {
    int h = i >> 3, d = i & 7;
    s.roWt[h][d] = roW[d * kH + h];
  }
  if (tid < kData) s.rob[tid] = rob[tid];
  __syncthreads();

  const float dt = __ldg(&ts[1]) - __ldg(&ts[0]);
  const float sqdt = sqrtf(dt);

  // ---- initial MLP: z0 (8) -> relu 128 -> relu 128 -> 64 ----
  if (tid < 256) {
    int j = tid & 127, pr = tid >> 7;
    float a0 = __ldg(&ib0[j]), a1 = a0;
#pragma unroll
    for (int k = 0; k < 8; ++k) {
      float w = __ldg(&iW0[j * 8 + k]);
      a0 = fmaf(w, __ldg(&z0[(bbase + 2 * pr) * 8 + k]), a0);
      a1 = fmaf(w, __ldg(&z0[(bbase + 2 * pr + 1) * 8 + k]), a1);
    }
    float* d0 = reinterpret_cast<float*>(&s.h0v4[j]) + 2 * pr;
    d0[0] = fmaxf(a0, 0.f); d0[1] = fmaxf(a1, 0.f);
  }
  __syncthreads();
  if (tid < 256) {
    int j = tid & 127, pr = tid >> 7;
    float a0 = __ldg(&ib1[j]), a1 = a0;
#pragma unroll 8
    for (int k = 0; k < kW; ++k) {
      float w = __ldg(&iW1[j * kW + k]);
      const float* x = reinterpret_cast<const float*>(&s.h0v4[k]) + 2 * pr;
      a0 = fmaf(w, x[0], a0);
      a1 = fmaf(w, x[1], a1);
    }
    float* d0 = reinterpret_cast<float*>(&s.h0c4[j]) + 2 * pr;
    d0[0] = fmaxf(a0, 0.f); d0[1] = fmaxf(a1, 0.f);
  }
  __syncthreads();
  if (tid < 256) {
    int b = tid >> 6, h = tid & 63;
    float acc = __ldg(&ib2[h]);
#pragma unroll 8
    for (int k = 0; k < kW; ++k)
      acc = fmaf(reinterpret_cast<const float*>(&s.h0c4[k])[b],
                 __ldg(&iW2[h * kW + k]), acc);
    reinterpret_cast<float*>(&s.ys4[h])[b] = acc;
  }
  __syncthreads();

  // per-thread constants
  const int netc = tid >> 8;            // phases A/B: 0 = v, 1 = c
  const int jA = tid & 127;
  const int prA = (tid >> 7) & 1;
  const int jD = (tid >> 1) & 127;      // phases D/E
  const int khD = tid & 1;
  const int prD = tid >> 8;
  const int j0 = tid << 1;              // diffusion col pair
  const int hC = tid >> 3;
  // drift in phase D: lane pairs
  const int pDr = tid >> 1;             // 0..255
  const int bDr = pDr >> 6, hDr = pDr & 63;
  const int kbDr = khD * 64;

  for (int st = 0; st < kSteps; ++st) {
    const float tcur = __ldg(&ts[st]);

    // ================= phase A: dense L0 of both nets + extras ===========
    if (tid >= 448) {
      int i = tid - 448;
      int b = i >> 4, n = i & 15;
      s.dws[b][n] = __ldg(&dW[((size_t)st * kB + bbase + b) * kNoise + n]) * sqdt;
    } else if (tid >= 416) {
      int i = tid - 416;
      int b = i >> 3, d = i & 7;
      float acc = s.rob[d];
#pragma unroll
      for (int h = 0; h < kH; ++h)
        acc = fmaf(reinterpret_cast<const float*>(&s.ys4[h])[b], s.roWt[h][d], acc);
      out[((size_t)(bbase + b) * kT + st) * kData + d] = acc;
    }
    {
      const float (*W0)[kW] = netc ? s.cW0t : s.vW0t;
      const float* bb = netc ? s.cb0 : s.vb0;
      float binit = fmaf(W0[0][jA], tcur, bb[jA]);
      u64 acc = pack2(binit, binit);
#pragma unroll 16
      for (int k = 1; k <= kH; ++k) {
        float w = W0[k][jA];
        u64 x2 = *reinterpret_cast<const u64*>(
            reinterpret_cast<const float*>(&s.ys4[k - 1]) + 2 * prA);
        acc = fma2(pack2(w, w), x2, acc);
      }
      float a0, a1; unpack2(acc, a0, a1);
      float* dst = reinterpret_cast<float*>(netc ? &s.h0c4[jA] : &s.h0v4[jA]) + 2 * prA;
      float2 r; r.x = lipswish(a0); r.y = lipswish(a1);
      *reinterpret_cast<float2*>(dst) = r;
    }
    __syncthreads();

    // ================= phase B: dense L1 of both nets ====================
    {
      const float (*W1)[kW] = netc ? s.cW1t : s.vW1t;
      const float* bb = netc ? s.cb1 : s.vb1;
      const float4* src = netc ? s.h0c4 : s.h0v4;
      float binit = bb[jA];
      u64 acc = pack2(binit, binit);
#pragma unroll 16
      for (int k = 0; k < kW; ++k) {
        float w = W1[k][jA];
        u64 x2 = *reinterpret_cast<const u64*>(
            reinterpret_cast<const float*>(&src[k]) + 2 * prA);
        acc = fma2(pack2(w, w), x2, acc);
      }
      float a0, a1; unpack2(acc, a0, a1);
      float* dst = reinterpret_cast<float*>(netc ? &s.h1c4[jA] : &s.h1v4[jA]) + 2 * prA;
      float2 r; r.x = lipswish(a0); r.y = lipswish(a1);
      *reinterpret_cast<float2*>(dst) = r;
    }
    __syncthreads();

    // ================= phase C: diffusion eval 1 (all threads) ===========
    {
      float p0, p1, p2, p3;
      diff_core(s, tid, j0, s.h1c4, p0, p1, p2, p3);
      if ((tid & 7) == 0) {
        float4 y = s.ys4[hC];
        float4 g; g.x = p0; g.y = p1; g.z = p2; g.w = p3;
        s.g04[hC] = g;
        float4 yp; yp.x = y.x + p0; yp.y = y.y + p1; yp.z = y.z + p2; yp.w = y.w + p3;
        s.yp4[hC] = yp;
      }
    }
    __syncthreads();

    // ================= phase D: c-net L0 at y' + drift final =============
    {
      float binit = (khD == 0) ? fmaf(s.cW0t[0][jD], tcur, s.cb0[jD]) : 0.f;
      u64 acc = pack2(binit, binit);
      int k0 = 1 + khD * 32;
#pragma unroll
      for (int k = k0; k < k0 + 32; ++k) {
        float w = s.cW0t[k][jD];
        u64 x2 = *reinterpret_cast<const u64*>(
            reinterpret_cast<const float*>(&s.yp4[k - 1]) + 2 * prD);
        acc = fma2(pack2(w, w), x2, acc);
      }
      float a0, a1; unpack2(acc, a0, a1);
      a0 += __shfl_xor_sync(~0u, a0, 1);
      a1 += __shfl_xor_sync(~0u, a1, 1);
      if (khD == 0) {
        float2 r; r.x = lipswish(a0); r.y = lipswish(a1);
        *reinterpret_cast<float2*>(
            reinterpret_cast<float*>(&s.h0c4[jD]) + 2 * prD) = r;
      }
    }
    {  // drift: output (bDr, hDr), k-half kbDr
      float acc = (khD == 0) ? s.vb2[hDr] : 0.f;
#pragma unroll 16
      for (int i = 0; i < 64; ++i) {
        int k = kbDr + i;
        acc = fmaf(reinterpret_cast<const float*>(&s.h1v4[k])[bDr],
                   __ldg(&g_vW2t[k * kH + hDr]), acc);
      }
      acc += __shfl_xor_sync(~0u, acc, 1);
      if (khD == 0)
        reinterpret_cast<float*>(&s.f04[hDr])[bDr] = s.vscl[hDr] * tanhf(acc) * dt;
    }
    __syncthreads();

    // ================= phase E: c-net L1 at y' ===========================
    {
      float binit = (khD == 0) ? s.cb1[jD] : 0.f;
      u64 acc = pack2(binit, binit);
      int k0 = khD * 64;
#pragma unroll 16
      for (int k = k0; k < k0 + 64; ++k) {
        float w = s.cW1t[k][jD];
        u64 x2 = *reinterpret_cast<const u64*>(
            reinterpret_cast<const float*>(&s.h0c4[k]) + 2 * prD);
        acc = fma2(pack2(w, w), x2, acc);
      }
      float a0, a1; unpack2(acc, a0, a1);
      a0 += __shfl_xor_sync(~0u, a0, 1);
      a1 += __shfl_xor_sync(~0u, a1, 1);
      if (khD == 0) {
        float2 r; r.x = lipswish(a0); r.y = lipswish(a1);
        *reinterpret_cast<float2*>(
            reinterpret_cast<float*>(&s.h1c4[jD]) + 2 * prD) = r;
      }
    }
    __syncthreads();

    // ================= phase F: diffusion eval 2 + Heun update ===========
    {
      float p0, p1, p2, p3;
      diff_core(s, tid, j0, s.h1c4, p0, p1, p2, p3);
      if ((tid & 7) == 0) {
        float4 y = s.ys4[hC];
        float4 f = s.f04[hC];
        float4 g = s.g04[hC];
        y.x += f.x + 0.5f * (g.x + p0);
        y.y += f.y + 0.5f * (g.y + p1);
        y.z += f.z + 0.5f * (g.z + p2);
        y.w += f.w + 0.5f * (g.w + p3);
        s.ys4[hC] = y;
      }
    }
    __syncthreads();
  }

  // final readout (index kSteps)
  if (tid < 32) {
    int b = tid >> 3, d = tid & 7;
    float acc = s.rob[d];
#pragma unroll
    for (int h = 0; h < kH; ++h)
      acc = fmaf(reinterpret_cast<const float*>(&s.ys4[h])[b], s.roWt[h][d], acc);
    out[((size_t)(bbase + b) * kT + kSteps) * kData + d] = acc;
  }
}

extern "C" void kernel_launch(void* const* d_in, const int* in_sizes, int n_in,
                              void* d_out, int out_size) {
  (void)in_sizes; (void)n_in; (void)out_size;
  const float* ts     = (const float*)d_in[0];
  const float* z0     = (const float*)d_in[1];
  const float* dW     = (const float*)d_in[2];
  const float* iW0    = (const float*)d_in[3];
  const float* ib0    = (const float*)d_in[4];
  const float* iW1    = (const float*)d_in[5];
  const float* ib1    = (const float*)d_in[6];
  const float* iW2    = (const float*)d_in[7];
  const float* ib2    = (const float*)d_in[8];
  const float* vW0    = (const float*)d_in[9];
  const float* vb0    = (const float*)d_in[10];
  const float* vW1    = (const float*)d_in[11];
  const float* vb1    = (const float*)d_in[12];
  const float* vW2    = (const float*)d_in[13];
  const float* vb2    = (const float*)d_in[14];
  const float* vscale = (const float*)d_in[15];
  const float* cW0    = (const float*)d_in[16];
  const float* cb0    = (const float*)d_in[17];
  const float* cW1    = (const float*)d_in[18];
  const float* cb1    = (const float*)d_in[19];
  const float* cW2    = (const float*)d_in[20];
  const float* cb2    = (const float*)d_in[21];
  const float* cscale = (const float*)d_in[22];
  const float* roW    = (const float*)d_in[23];
  const float* rob    = (const float*)d_in[24];

  cudaFuncSetAttribute(sde_kernel, cudaFuncAttributeMaxDynamicSharedMemorySize,
                       (int)sizeof(Smem));

  transpose_kernel<<<148, 256>>>(cW2, vW2);
  sde_kernel<<<NCTA, NTHR, sizeof(Smem)>>>(
      ts, z0, dW, iW0, ib0, iW1, ib1, iW2, ib2,
      vW0, vb0, vW1, vb1, vb2, vscale,
      cW0, cb0, cW1, cb1, cb2, cscale, roW, rob,
      (float*)d_out);
}

// round 5
// speedup vs baseline: 1.6388x; 1.6388x over previous
#include <cuda_runtime.h>
#include <math.h>

// ---------------------------------------------------------------------------
// NeuralSDE (Euler-Heun / Stratonovich) persistent kernel, round 4.
// Base = round-2 kernel (best, 25.7ms). Changes: diffusion k-loop unroll 8,
// drift final layer moved from phase C to phase D (lane-pair k-split).
// ---------------------------------------------------------------------------

#define kH     64
#define kNoise 16
#define kData  8
#define kW     128
#define kB     512
#define kT     1025
#define kSteps 1024
#define BS     4
#define NCTA   128
#define NTHR   512
#define kCO    1024

using u64 = unsigned long long;

// Transposed big weights (k-major). 8B-aligned for packed loads.
__device__ u64   g_cW2t[kW * kCO / 2];   // float (k,j) at k*1024 + j
__device__ float g_vW2t[kW * kH];        // float (k,h) at k*64 + h

struct Smem {
  float vW0t[65][kW];
  float cW0t[65][kW];
  float vW1t[kW][kW];
  float cW1t[kW][kW];
  float vb0[kW], vb1[kW], cb0[kW], cb1[kW];
  float vb2[kH], vscl[kH];
  float cb2[kCO];
  float cscl[kCO];
  float roWt[kH][kData];
  float rob[kData];
  // activations: float4 over the 4 samples
  float4 ys4[kH];
  float4 g04[kH];
  float4 f04[kH];
  float4 yp4[kH];
  float4 h0v4[kW];
  float4 h0c4[kW];
  float4 h1v4[kW];
  float4 h1c4[kW];
  float  dws[BS][kNoise];
};

__global__ void transpose_kernel(const float* __restrict__ cW2,
                                 const float* __restrict__ vW2) {
  int idx = blockIdx.x * blockDim.x + threadIdx.x;
  int stride = gridDim.x * blockDim.x;
  float* ct = reinterpret_cast<float*>(g_cW2t);
  for (int i = idx; i < kW * kCO; i += stride) {
    int k = i >> 10, j = i & (kCO - 1);
    ct[i] = cW2[j * kW + k];            // cW2 is (1024, 128) row-major
  }
  for (int i = idx; i < kW * kH; i += stride) {
    int k = i >> 6, h = i & (kH - 1);
    g_vW2t[i] = vW2[h * kW + k];        // vW2 is (64, 128) row-major
  }
}

__device__ __forceinline__ u64 pack2(float lo, float hi) {
  u64 r; asm("mov.b64 %0,{%1,%2};" : "=l"(r) : "f"(lo), "f"(hi)); return r;
}
__device__ __forceinline__ void unpack2(u64 v, float& lo, float& hi) {
  asm("mov.b64 {%0,%1},%2;" : "=f"(lo), "=f"(hi) : "l"(v));
}
__device__ __forceinline__ u64 fma2(u64 a, u64 b, u64 c) {
  u64 d; asm("fma.rn.f32x2 %0,%1,%2,%3;" : "=l"(d) : "l"(a), "l"(b), "l"(c));
  return d;
}

__device__ __forceinline__ float lipswish(float x) {
  return 0.909f * x * (1.0f / (1.0f + expf(-x)));
}

__global__ __launch_bounds__(NTHR, 1) void sde_kernel(
    const float* __restrict__ ts, const float* __restrict__ z0,
    const float* __restrict__ dW,
    const float* __restrict__ iW0, const float* __restrict__ ib0,
    const float* __restrict__ iW1, const float* __restrict__ ib1,
    const float* __restrict__ iW2, const float* __restrict__ ib2,
    const float* __restrict__ vW0, const float* __restrict__ vb0,
    const float* __restrict__ vW1, const float* __restrict__ vb1,
    const float* __restrict__ vb2, const float* __restrict__ vscale,
    const float* __restrict__ cW0, const float* __restrict__ cb0,
    const float* __restrict__ cW1, const float* __restrict__ cb1,
    const float* __restrict__ cb2, const float* __restrict__ cscale,
    const float* __restrict__ roW, const float* __restrict__ rob,
    float* __restrict__ out) {
  extern __shared__ char smem_raw[];
  Smem& s = *reinterpret_cast<Smem*>(smem_raw);
  const int tid = threadIdx.x;
  const int bbase = blockIdx.x * BS;

  // ---- load small weights transposed into smem ----
  for (int i = tid; i < 65 * kW; i += NTHR) {
    int k = i >> 7, j = i & 127;
    s.vW0t[k][j] = vW0[j * 65 + k];
    s.cW0t[k][j] = cW0[j * 65 + k];
  }
  for (int i = tid; i < kW * kW; i += NTHR) {
    int k = i >> 7, j = i & 127;
    s.vW1t[k][j] = vW1[j * kW + k];
    s.cW1t[k][j] = cW1[j * kW + k];
  }
  for (int i = tid; i < kW; i += NTHR) {
    s.vb0[i] = vb0[i]; s.vb1[i] = vb1[i];
    s.cb0[i] = cb0[i]; s.cb1[i] = cb1[i];
  }
  for (int i = tid; i < kH; i += NTHR) { s.vb2[i] = vb2[i]; s.vscl[i] = vscale[i]; }
  for (int i = tid; i < kCO; i += NTHR) { s.cb2[i] = cb2[i]; s.cscl[i] = cscale[i]; }
  for (int i = tid; i < kH * kData; i += NTHR) {
    int h = i >> 3, d = i & 7;
    s.roWt[h][d] = roW[d * kH + h];
  }
  if (tid < kData) s.rob[tid] = rob[tid];
  __syncthreads();

  const float dt = __ldg(&ts[1]) - __ldg(&ts[0]);
  const float sqdt = sqrtf(dt);

  // ---- initial MLP: z0 (8) -> relu 128 -> relu 128 -> 64 ----
  if (tid < 256) {
    int j = tid & 127, pr = tid >> 7;  // samples 2pr, 2pr+1
    float a0 = __ldg(&ib0[j]), a1 = a0;
#pragma unroll
    for (int k = 0; k < 8; ++k) {
      float w = __ldg(&iW0[j * 8 + k]);
      a0 = fmaf(w, __ldg(&z0[(bbase + 2 * pr) * 8 + k]), a0);
      a1 = fmaf(w, __ldg(&z0[(bbase + 2 * pr + 1) * 8 + k]), a1);
    }
    float* d0 = reinterpret_cast<float*>(&s.h0v4[j]) + 2 * pr;
    d0[0] = fmaxf(a0, 0.f); d0[1] = fmaxf(a1, 0.f);
  }
  __syncthreads();
  if (tid < 256) {
    int j = tid & 127, pr = tid >> 7;
    float a0 = __ldg(&ib1[j]), a1 = a0;
#pragma unroll 4
    for (int k = 0; k < kW; ++k) {
      float w = __ldg(&iW1[j * kW + k]);
      const float* x = reinterpret_cast<const float*>(&s.h0v4[k]) + 2 * pr;
      a0 = fmaf(w, x[0], a0);
      a1 = fmaf(w, x[1], a1);
    }
    float* d0 = reinterpret_cast<float*>(&s.h0c4[j]) + 2 * pr;  // temp
    d0[0] = fmaxf(a0, 0.f); d0[1] = fmaxf(a1, 0.f);
  }
  __syncthreads();
  if (tid < 256) {
    int b = tid >> 6, h = tid & 63;
    float acc = __ldg(&ib2[h]);
#pragma unroll 4
    for (int k = 0; k < kW; ++k)
      acc = fmaf(reinterpret_cast<const float*>(&s.h0c4[k])[b],
                 __ldg(&iW2[h * kW + k]), acc);
    reinterpret_cast<float*>(&s.ys4[h])[b] = acc;
  }
  __syncthreads();

  // precomputed per-thread constants
  const int netc = tid >> 8;            // 0 = v, 1 = c (phases A/B)
  const int jA = tid & 127;
  const int prA = (tid >> 7) & 1;       // sample pair (0: b0,b1; 1: b2,b3)
  const int jD = (tid >> 1) & 127;      // phases D/E
  const int khD = tid & 1;
  const int prD = tid >> 8;
  const int j0 = tid << 1;              // diffusion col pair
  const int hC = tid >> 3;              // diffusion h
  const u64* wrowC = g_cW2t + tid;      // row k at + k*512 (u64 units)
  // drift in phase D: lane pairs
  const int pDr = tid >> 1;             // 0..255
  const int bDr = pDr >> 6, hDr = pDr & 63;
  const int kbDr = khD * 64;

  for (int st = 0; st < kSteps; ++st) {
    const float tcur = __ldg(&ts[st]);

    // ================= phase A =================
    // extras first (latency overlap): dW load + readout of current ys (index st)
    if (tid >= 448) {
      int i = tid - 448;                 // 64 tasks
      int b = i >> 4, n = i & 15;
      s.dws[b][n] = __ldg(&dW[((size_t)st * kB + bbase + b) * kNoise + n]) * sqdt;
    } else if (tid >= 416) {
      int i = tid - 416;                 // 32 tasks
      int b = i >> 3, d = i & 7;
      float acc = s.rob[d];
#pragma unroll
      for (int h = 0; h < kH; ++h)
        acc = fmaf(reinterpret_cast<const float*>(&s.ys4[h])[b], s.roWt[h][d], acc);
      out[((size_t)(bbase + b) * kT + st) * kData + d] = acc;
    }
    // dense layer 0 of BOTH nets: x = (t, ys)
    {
      const float (*W0)[kW] = netc ? s.cW0t : s.vW0t;
      const float* bb = netc ? s.cb0 : s.vb0;
      float binit = fmaf(W0[0][jA], tcur, bb[jA]);
      u64 acc = pack2(binit, binit);
#pragma unroll 8
      for (int k = 1; k <= kH; ++k) {
        float w = W0[k][jA];
        u64 x2 = *reinterpret_cast<const u64*>(
            reinterpret_cast<const float*>(&s.ys4[k - 1]) + 2 * prA);
        acc = fma2(pack2(w, w), x2, acc);
      }
      float a0, a1; unpack2(acc, a0, a1);
      float* dst = reinterpret_cast<float*>(netc ? &s.h0c4[jA] : &s.h0v4[jA]) + 2 * prA;
      float2 r; r.x = lipswish(a0); r.y = lipswish(a1);
      *reinterpret_cast<float2*>(dst) = r;
    }
    __syncthreads();

    // ================= phase B: dense layer 1 of both nets =================
    {
      const float (*W1)[kW] = netc ? s.cW1t : s.vW1t;
      const float* bb = netc ? s.cb1 : s.vb1;
      const float4* src = netc ? s.h0c4 : s.h0v4;
      float binit = bb[jA];
      u64 acc = pack2(binit, binit);
#pragma unroll 8
      for (int k = 0; k < kW; ++k) {
        float w = W1[k][jA];
        u64 x2 = *reinterpret_cast<const u64*>(
            reinterpret_cast<const float*>(&src[k]) + 2 * prA);
        acc = fma2(pack2(w, w), x2, acc);
      }
      float a0, a1; unpack2(acc, a0, a1);
      float* dst = reinterpret_cast<float*>(netc ? &s.h1c4[jA] : &s.h1v4[jA]) + 2 * prA;
      float2 r; r.x = lipswish(a0); r.y = lipswish(a1);
      *reinterpret_cast<float2*>(dst) = r;
    }
    __syncthreads();

    // ================= phase C: diffusion eval 1 =================
    {
      u64 bias2 = *reinterpret_cast<const u64*>(&s.cb2[j0]);
      u64 A0 = bias2, A1 = bias2, A2 = bias2, A3 = bias2;
#pragma unroll 8
      for (int k = 0; k < kW; ++k) {
        u64 w2 = wrowC[(size_t)k * (kCO / 2)];
        float4 x = s.h1c4[k];
        A0 = fma2(w2, pack2(x.x, x.x), A0);
        A1 = fma2(w2, pack2(x.y, x.y), A1);
        A2 = fma2(w2, pack2(x.z, x.z), A2);
        A3 = fma2(w2, pack2(x.w, x.w), A3);
      }
      float csx = s.cscl[j0], csy = s.cscl[j0 + 1];
      int n0 = j0 & (kNoise - 1);
      float2 d0 = *reinterpret_cast<const float2*>(&s.dws[0][n0]);
      float2 d1 = *reinterpret_cast<const float2*>(&s.dws[1][n0]);
      float2 d2 = *reinterpret_cast<const float2*>(&s.dws[2][n0]);
      float2 d3 = *reinterpret_cast<const float2*>(&s.dws[3][n0]);
      float lo, hi;
      unpack2(A0, lo, hi); float p0 = tanhf(lo) * csx * d0.x + tanhf(hi) * csy * d0.y;
      unpack2(A1, lo, hi); float p1 = tanhf(lo) * csx * d1.x + tanhf(hi) * csy * d1.y;
      unpack2(A2, lo, hi); float p2 = tanhf(lo) * csx * d2.x + tanhf(hi) * csy * d2.y;
      unpack2(A3, lo, hi); float p3 = tanhf(lo) * csx * d3.x + tanhf(hi) * csy * d3.y;
      p0 += __shfl_xor_sync(~0u, p0, 1); p0 += __shfl_xor_sync(~0u, p0, 2); p0 += __shfl_xor_sync(~0u, p0, 4);
      p1 += __shfl_xor_sync(~0u, p1, 1); p1 += __shfl_xor_sync(~0u, p1, 2); p1 += __shfl_xor_sync(~0u, p1, 4);
      p2 += __shfl_xor_sync(~0u, p2, 1); p2 += __shfl_xor_sync(~0u, p2, 2); p2 += __shfl_xor_sync(~0u, p2, 4);
      p3 += __shfl_xor_sync(~0u, p3, 1); p3 += __shfl_xor_sync(~0u, p3, 2); p3 += __shfl_xor_sync(~0u, p3, 4);
      if ((tid & 7) == 0) {
        float4 y = s.ys4[hC];
        float4 g; g.x = p0; g.y = p1; g.z = p2; g.w = p3;
        s.g04[hC] = g;
        float4 yp; yp.x = y.x + p0; yp.y = y.y + p1; yp.z = y.z + p2; yp.w = y.w + p3;
        s.yp4[hC] = yp;
      }
    }
    __syncthreads();

    // ================= phase D: c-net layer 0 at y' + drift final ========
    {
      float binit = (khD == 0) ? fmaf(s.cW0t[0][jD], tcur, s.cb0[jD]) : 0.f;
      u64 acc = pack2(binit, binit);
      int k0 = 1 + khD * 32;
#pragma unroll 8
      for (int k = k0; k < k0 + 32; ++k) {
        float w = s.cW0t[k][jD];
        u64 x2 = *reinterpret_cast<const u64*>(
            reinterpret_cast<const float*>(&s.yp4[k - 1]) + 2 * prD);
        acc = fma2(pack2(w, w), x2, acc);
      }
      float a0, a1; unpack2(acc, a0, a1);
      a0 += __shfl_xor_sync(~0u, a0, 1);
      a1 += __shfl_xor_sync(~0u, a1, 1);
      if (khD == 0) {
        float2 r; r.x = lipswish(a0); r.y = lipswish(a1);
        *reinterpret_cast<float2*>(
            reinterpret_cast<float*>(&s.h0c4[jD]) + 2 * prD) = r;
      }
    }
    {  // drift final layer: output (bDr, hDr), k-half kbDr
      float acc = (khD == 0) ? s.vb2[hDr] : 0.f;
#pragma unroll 8
      for (int i = 0; i < 64; ++i) {
        int k = kbDr + i;
        acc = fmaf(reinterpret_cast<const float*>(&s.h1v4[k])[bDr],
                   __ldg(&g_vW2t[k * kH + hDr]), acc);
      }
      acc += __shfl_xor_sync(~0u, acc, 1);
      if (khD == 0)
        reinterpret_cast<float*>(&s.f04[hDr])[bDr] = s.vscl[hDr] * tanhf(acc) * dt;
    }
    __syncthreads();

    // ================= phase E: c-net layer 1 at y' =================
    {
      float binit = (khD == 0) ? s.cb1[jD] : 0.f;
      u64 acc = pack2(binit, binit);
      int k0 = khD * 64;
#pragma unroll 8
      for (int k = k0; k < k0 + 64; ++k) {
        float w = s.cW1t[k][jD];
        u64 x2 = *reinterpret_cast<const u64*>(
            reinterpret_cast<const float*>(&s.h0c4[k]) + 2 * prD);
        acc = fma2(pack2(w, w), x2, acc);
      }
      float a0, a1; unpack2(acc, a0, a1);
      a0 += __shfl_xor_sync(~0u, a0, 1);
      a1 += __shfl_xor_sync(~0u, a1, 1);
      if (khD == 0) {
        float2 r; r.x = lipswish(a0); r.y = lipswish(a1);
        *reinterpret_cast<float2*>(
            reinterpret_cast<float*>(&s.h1c4[jD]) + 2 * prD) = r;
      }
    }
    __syncthreads();

    // ================= phase F: diffusion eval 2 + Heun update ===========
    {
      u64 bias2 = *reinterpret_cast<const u64*>(&s.cb2[j0]);
      u64 A0 = bias2, A1 = bias2, A2 = bias2, A3 = bias2;
#pragma unroll 8
      for (int k = 0; k < kW; ++k) {
        u64 w2 = wrowC[(size_t)k * (kCO / 2)];
        float4 x = s.h1c4[k];
        A0 = fma2(w2, pack2(x.x, x.x), A0);
        A1 = fma2(w2, pack2(x.y, x.y), A1);
        A2 = fma2(w2, pack2(x.z, x.z), A2);
        A3 = fma2(w2, pack2(x.w, x.w), A3);
      }
      float csx = s.cscl[j0], csy = s.cscl[j0 + 1];
      int n0 = j0 & (kNoise - 1);
      float2 d0 = *reinterpret_cast<const float2*>(&s.dws[0][n0]);
      float2 d1 = *reinterpret_cast<const float2*>(&s.dws[1][n0]);
      float2 d2 = *reinterpret_cast<const float2*>(&s.dws[2][n0]);
      float2 d3 = *reinterpret_cast<const float2*>(&s.dws[3][n0]);
      float lo, hi;
      unpack2(A0, lo, hi); float p0 = tanhf(lo) * csx * d0.x + tanhf(hi) * csy * d0.y;
      unpack2(A1, lo, hi); float p1 = tanhf(lo) * csx * d1.x + tanhf(hi) * csy * d1.y;
      unpack2(A2, lo, hi); float p2 = tanhf(lo) * csx * d2.x + tanhf(hi) * csy * d2.y;
      unpack2(A3, lo, hi); float p3 = tanhf(lo) * csx * d3.x + tanhf(hi) * csy * d3.y;
      p0 += __shfl_xor_sync(~0u, p0, 1); p0 += __shfl_xor_sync(~0u, p0, 2); p0 += __shfl_xor_sync(~0u, p0, 4);
      p1 += __shfl_xor_sync(~0u, p1, 1); p1 += __shfl_xor_sync(~0u, p1, 2); p1 += __shfl_xor_sync(~0u, p1, 4);
      p2 += __shfl_xor_sync(~0u, p2, 1); p2 += __shfl_xor_sync(~0u, p2, 2); p2 += __shfl_xor_sync(~0u, p2, 4);
      p3 += __shfl_xor_sync(~0u, p3, 1); p3 += __shfl_xor_sync(~0u, p3, 2); p3 += __shfl_xor_sync(~0u, p3, 4);
      if ((tid & 7) == 0) {
        float4 y = s.ys4[hC];
        float4 f = s.f04[hC];
        float4 g = s.g04[hC];
        y.x += f.x + 0.5f * (g.x + p0);
        y.y += f.y + 0.5f * (g.y + p1);
        y.z += f.z + 0.5f * (g.z + p2);
        y.w += f.w + 0.5f * (g.w + p3);
        s.ys4[hC] = y;
      }
    }
    __syncthreads();
  }

  // final readout (index kSteps)
  if (tid < 32) {
    int b = tid >> 3, d = tid & 7;
    float acc = s.rob[d];
#pragma unroll
    for (int h = 0; h < kH; ++h)
      acc = fmaf(reinterpret_cast<const float*>(&s.ys4[h])[b], s.roWt[h][d], acc);
    out[((size_t)(bbase + b) * kT + kSteps) * kData + d] = acc;
  }
}

extern "C" void kernel_launch(void* const* d_in, const int* in_sizes, int n_in,
                              void* d_out, int out_size) {
  (void)in_sizes; (void)n_in; (void)out_size;
  const float* ts     = (const float*)d_in[0];
  const float* z0     = (const float*)d_in[1];
  const float* dW     = (const float*)d_in[2];
  const float* iW0    = (const float*)d_in[3];
  const float* ib0    = (const float*)d_in[4];
  const float* iW1    = (const float*)d_in[5];
  const float* ib1    = (const float*)d_in[6];
  const float* iW2    = (const float*)d_in[7];
  const float* ib2    = (const float*)d_in[8];
  const float* vW0    = (const float*)d_in[9];
  const float* vb0    = (const float*)d_in[10];
  const float* vW1    = (const float*)d_in[11];
  const float* vb1    = (const float*)d_in[12];
  const float* vW2    = (const float*)d_in[13];
  const float* vb2    = (const float*)d_in[14];
  const float* vscale = (const float*)d_in[15];
  const float* cW0    = (const float*)d_in[16];
  const float* cb0    = (const float*)d_in[17];
  const float* cW1    = (const float*)d_in[18];
  const float* cb1    = (const float*)d_in[19];
  const float* cW2    = (const float*)d_in[20];
  const float* cb2    = (const float*)d_in[21];
  const float* cscale = (const float*)d_in[22];
  const float* roW    = (const float*)d_in[23];
  const float* rob    = (const float*)d_in[24];

  cudaFuncSetAttribute(sde_kernel, cudaFuncAttributeMaxDynamicSharedMemorySize,
                       (int)sizeof(Smem));

  transpose_kernel<<<148, 256>>>(cW2, vW2);
  sde_kernel<<<NCTA, NTHR, sizeof(Smem)>>>(
      ts, z0, dW, iW0, ib0, iW1, ib1, iW2, ib2,
      vW0, vb0, vW1, vb1, vb2, vscale,
      cW0, cb0, cW1, cb1, cb2, cscale, roW, rob,
      (float*)d_out);
}

// round 6
// speedup vs baseline: 1.8813x; 1.1480x over previous
#include <cuda_runtime.h>
#include <math.h>

// ---------------------------------------------------------------------------
// NeuralSDE (Euler-Heun / Stratonovich) persistent kernel, round 5.
// Base = round-4 kernel (19.9ms). Change: warp-specialized small dense layers
// (one thread per (net,j) with ALL 4 samples) to eliminate redundant /
// bank-conflicted L1 wavefronts. Diffusion phases C/F unchanged.
// ---------------------------------------------------------------------------

#define kH     64
#define kNoise 16
#define kData  8
#define kW     128
#define kB     512
#define kT     1025
#define kSteps 1024
#define BS     4
#define NCTA   128
#define NTHR   512
#define kCO    1024

using u64 = unsigned long long;

// Transposed big weights (k-major). 8B-aligned for packed loads.
__device__ u64   g_cW2t[kW * kCO / 2];   // float (k,j) at k*1024 + j
__device__ float g_vW2t[kW * kH];        // float (k,h) at k*64 + h

struct Smem {
  float vW0t[65][kW];
  float cW0t[65][kW];
  float vW1t[kW][kW];
  float cW1t[kW][kW];
  float vb0[kW], vb1[kW], cb0[kW], cb1[kW];
  float vb2[kH], vscl[kH];
  float cb2[kCO];
  float cscl[kCO];
  float roWt[kH][kData];
  float rob[kData];
  // activations: float4 over the 4 samples
  float4 ys4[kH];
  float4 g04[kH];
  float4 f04[kH];
  float4 yp4[kH];
  float4 h0v4[kW];
  float4 h0c4[kW];
  float4 h1v4[kW];
  float4 h1c4[kW];
  float  dws[BS][kNoise];
};

__global__ void transpose_kernel(const float* __restrict__ cW2,
                                 const float* __restrict__ vW2) {
  int idx = blockIdx.x * blockDim.x + threadIdx.x;
  int stride = gridDim.x * blockDim.x;
  float* ct = reinterpret_cast<float*>(g_cW2t);
  for (int i = idx; i < kW * kCO; i += stride) {
    int k = i >> 10, j = i & (kCO - 1);
    ct[i] = cW2[j * kW + k];            // cW2 is (1024, 128) row-major
  }
  for (int i = idx; i < kW * kH; i += stride) {
    int k = i >> 6, h = i & (kH - 1);
    g_vW2t[i] = vW2[h * kW + k];        // vW2 is (64, 128) row-major
  }
}

__device__ __forceinline__ u64 pack2(float lo, float hi) {
  u64 r; asm("mov.b64 %0,{%1,%2};" : "=l"(r) : "f"(lo), "f"(hi)); return r;
}
__device__ __forceinline__ void unpack2(u64 v, float& lo, float& hi) {
  asm("mov.b64 {%0,%1},%2;" : "=f"(lo), "=f"(hi) : "l"(v));
}
__device__ __forceinline__ u64 fma2(u64 a, u64 b, u64 c) {
  u64 d; asm("fma.rn.f32x2 %0,%1,%2,%3;" : "=l"(d) : "l"(a), "l"(b), "l"(c));
  return d;
}
__device__ __forceinline__ u64 add2(u64 a, u64 b) {
  u64 d; asm("add.rn.f32x2 %0,%1,%2;" : "=l"(d) : "l"(a), "l"(b));
  return d;
}

__device__ __forceinline__ float lipswish(float x) {
  return 0.909f * x * (1.0f / (1.0f + expf(-x)));
}

// One (net,j) output for all 4 samples: acc over k in [k0, k0+n) of Wt[k][j] *
// x4[k - xoff], dual accumulator pairs. Returns float4 of the 4 raw sums.
__device__ __forceinline__ float4 dense4(const float (*Wt)[kW], int j,
                                         const float4* __restrict__ x4,
                                         int k0, int n, float bias0) {
  u64 a01 = pack2(bias0, bias0), a23 = a01;
  u64 b01 = pack2(0.f, 0.f), b23 = b01;
#pragma unroll 4
  for (int k = k0; k < k0 + n; k += 2) {
    float wa = Wt[k][j];
    ulonglong2 xa = *reinterpret_cast<const ulonglong2*>(&x4[k - k0]);
    u64 wa2 = pack2(wa, wa);
    a01 = fma2(wa2, xa.x, a01);
    a23 = fma2(wa2, xa.y, a23);
    float wb = Wt[k + 1][j];
    ulonglong2 xb = *reinterpret_cast<const ulonglong2*>(&x4[k + 1 - k0]);
    u64 wb2 = pack2(wb, wb);
    b01 = fma2(wb2, xb.x, b01);
    b23 = fma2(wb2, xb.y, b23);
  }
  a01 = add2(a01, b01);
  a23 = add2(a23, b23);
  float4 r;
  unpack2(a01, r.x, r.y);
  unpack2(a23, r.z, r.w);
  return r;
}

__global__ __launch_bounds__(NTHR, 1) void sde_kernel(
    const float* __restrict__ ts, const float* __restrict__ z0,
    const float* __restrict__ dW,
    const float* __restrict__ iW0, const float* __restrict__ ib0,
    const float* __restrict__ iW1, const float* __restrict__ ib1,
    const float* __restrict__ iW2, const float* __restrict__ ib2,
    const float* __restrict__ vW0, const float* __restrict__ vb0,
    const float* __restrict__ vW1, const float* __restrict__ vb1,
    const float* __restrict__ vb2, const float* __restrict__ vscale,
    const float* __restrict__ cW0, const float* __restrict__ cb0,
    const float* __restrict__ cW1, const float* __restrict__ cb1,
    const float* __restrict__ cb2, const float* __restrict__ cscale,
    const float* __restrict__ roW, const float* __restrict__ rob,
    float* __restrict__ out) {
  extern __shared__ char smem_raw[];
  Smem& s = *reinterpret_cast<Smem*>(smem_raw);
  const int tid = threadIdx.x;
  const int bbase = blockIdx.x * BS;

  // ---- load small weights transposed into smem ----
  for (int i = tid; i < 65 * kW; i += NTHR) {
    int k = i >> 7, j = i & 127;
    s.vW0t[k][j] = vW0[j * 65 + k];
    s.cW0t[k][j] = cW0[j * 65 + k];
  }
  for (int i = tid; i < kW * kW; i += NTHR) {
    int k = i >> 7, j = i & 127;
    s.vW1t[k][j] = vW1[j * kW + k];
    s.cW1t[k][j] = cW1[j * kW + k];
  }
  for (int i = tid; i < kW; i += NTHR) {
    s.vb0[i] = vb0[i]; s.vb1[i] = vb1[i];
    s.cb0[i] = cb0[i]; s.cb1[i] = cb1[i];
  }
  for (int i = tid; i < kH; i += NTHR) { s.vb2[i] = vb2[i]; s.vscl[i] = vscale[i]; }
  for (int i = tid; i < kCO; i += NTHR) { s.cb2[i] = cb2[i]; s.cscl[i] = cscale[i]; }
  for (int i = tid; i < kH * kData; i += NTHR) {
    int h = i >> 3, d = i & 7;
    s.roWt[h][d] = roW[d * kH + h];
  }
  if (tid < kData) s.rob[tid] = rob[tid];
  __syncthreads();

  const float dt = __ldg(&ts[1]) - __ldg(&ts[0]);
  const float sqdt = sqrtf(dt);

  // ---- initial MLP: z0 (8) -> relu 128 -> relu 128 -> 64 ----
  if (tid < 256) {
    int j = tid & 127, pr = tid >> 7;  // samples 2pr, 2pr+1
    float a0 = __ldg(&ib0[j]), a1 = a0;
#pragma unroll
    for (int k = 0; k < 8; ++k) {
      float w = __ldg(&iW0[j * 8 + k]);
      a0 = fmaf(w, __ldg(&z0[(bbase + 2 * pr) * 8 + k]), a0);
      a1 = fmaf(w, __ldg(&z0[(bbase + 2 * pr + 1) * 8 + k]), a1);
    }
    float* d0 = reinterpret_cast<float*>(&s.h0v4[j]) + 2 * pr;
    d0[0] = fmaxf(a0, 0.f); d0[1] = fmaxf(a1, 0.f);
  }
  __syncthreads();
  if (tid < 256) {
    int j = tid & 127, pr = tid >> 7;
    float a0 = __ldg(&ib1[j]), a1 = a0;
#pragma unroll 4
    for (int k = 0; k < kW; ++k) {
      float w = __ldg(&iW1[j * kW + k]);
      const float* x = reinterpret_cast<const float*>(&s.h0v4[k]) + 2 * pr;
      a0 = fmaf(w, x[0], a0);
      a1 = fmaf(w, x[1], a1);
    }
    float* d0 = reinterpret_cast<float*>(&s.h0c4[j]) + 2 * pr;  // temp
    d0[0] = fmaxf(a0, 0.f); d0[1] = fmaxf(a1, 0.f);
  }
  __syncthreads();
  if (tid < 256) {
    int b = tid >> 6, h = tid & 63;
    float acc = __ldg(&ib2[h]);
#pragma unroll 4
    for (int k = 0; k < kW; ++k)
      acc = fmaf(reinterpret_cast<const float*>(&s.h0c4[k])[b],
                 __ldg(&iW2[h * kW + k]), acc);
    reinterpret_cast<float*>(&s.ys4[h])[b] = acc;
  }
  __syncthreads();

  // precomputed per-thread constants
  const int jA = tid & 127;             // phases A/B: (net, j), 4 samples
  const int netA = tid >> 7;            // valid for tid < 256
  const int j0 = tid << 1;              // diffusion col pair (phases C/F)
  const int hC = tid >> 3;              // diffusion h
  const u64* wrowC = g_cW2t + tid;      // row k at + k*512 (u64 units)
  const int hDr = tid - 256;            // drift h (tid in [256,320))

  for (int st = 0; st < kSteps; ++st) {
    const float tcur = __ldg(&ts[st]);

    // ================= phase A: dense L0 of both nets + extras ===========
    if (tid < 256) {
      const float (*W0)[kW] = netA ? s.cW0t : s.vW0t;
      const float* bb = netA ? s.cb0 : s.vb0;
      float bi = fmaf(W0[0][jA], tcur, bb[jA]);
      float4 r = dense4(&W0[1], jA, s.ys4, 0, kH, bi);
      float4 h; h.x = lipswish(r.x); h.y = lipswish(r.y);
      h.z = lipswish(r.z); h.w = lipswish(r.w);
      (netA ? s.h0c4 : s.h0v4)[jA] = h;
    } else if (tid >= 448) {
      int i = tid - 448;                 // 64 tasks: dW load
      int b = i >> 4, n = i & 15;
      s.dws[b][n] = __ldg(&dW[((size_t)st * kB + bbase + b) * kNoise + n]) * sqdt;
    } else if (tid >= 416) {
      int i = tid - 416;                 // 32 tasks: readout of y_st
      int b = i >> 3, d = i & 7;
      float acc = s.rob[d];
#pragma unroll
      for (int h = 0; h < kH; ++h)
        acc = fmaf(reinterpret_cast<const float*>(&s.ys4[h])[b], s.roWt[h][d], acc);
      out[((size_t)(bbase + b) * kT + st) * kData + d] = acc;
    }
    __syncthreads();

    // ================= phase B: dense L1 of both nets ====================
    if (tid < 256) {
      const float (*W1)[kW] = netA ? s.cW1t : s.vW1t;
      const float* bb = netA ? s.cb1 : s.vb1;
      const float4* src = netA ? s.h0c4 : s.h0v4;
      float4 r = dense4(W1, jA, src, 0, kW, bb[jA]);
      float4 h; h.x = lipswish(r.x); h.y = lipswish(r.y);
      h.z = lipswish(r.z); h.w = lipswish(r.w);
      (netA ? s.h1c4 : s.h1v4)[jA] = h;
    }
    __syncthreads();

    // ================= phase C: diffusion eval 1 (all threads) ===========
    {
      u64 bias2 = *reinterpret_cast<const u64*>(&s.cb2[j0]);
      u64 A0 = bias2, A1 = bias2, A2 = bias2, A3 = bias2;
#pragma unroll 8
      for (int k = 0; k < kW; ++k) {
        u64 w2 = wrowC[(size_t)k * (kCO / 2)];
        float4 x = s.h1c4[k];
        A0 = fma2(w2, pack2(x.x, x.x), A0);
        A1 = fma2(w2, pack2(x.y, x.y), A1);
        A2 = fma2(w2, pack2(x.z, x.z), A2);
        A3 = fma2(w2, pack2(x.w, x.w), A3);
      }
      float csx = s.cscl[j0], csy = s.cscl[j0 + 1];
      int n0 = j0 & (kNoise - 1);
      float2 d0 = *reinterpret_cast<const float2*>(&s.dws[0][n0]);
      float2 d1 = *reinterpret_cast<const float2*>(&s.dws[1][n0]);
      float2 d2 = *reinterpret_cast<const float2*>(&s.dws[2][n0]);
      float2 d3 = *reinterpret_cast<const float2*>(&s.dws[3][n0]);
      float lo, hi;
      unpack2(A0, lo, hi); float p0 = tanhf(lo) * csx * d0.x + tanhf(hi) * csy * d0.y;
      unpack2(A1, lo, hi); float p1 = tanhf(lo) * csx * d1.x + tanhf(hi) * csy * d1.y;
      unpack2(A2, lo, hi); float p2 = tanhf(lo) * csx * d2.x + tanhf(hi) * csy * d2.y;
      unpack2(A3, lo, hi); float p3 = tanhf(lo) * csx * d3.x + tanhf(hi) * csy * d3.y;
      p0 += __shfl_xor_sync(~0u, p0, 1); p0 += __shfl_xor_sync(~0u, p0, 2); p0 += __shfl_xor_sync(~0u, p0, 4);
      p1 += __shfl_xor_sync(~0u, p1, 1); p1 += __shfl_xor_sync(~0u, p1, 2); p1 += __shfl_xor_sync(~0u, p1, 4);
      p2 += __shfl_xor_sync(~0u, p2, 1); p2 += __shfl_xor_sync(~0u, p2, 2); p2 += __shfl_xor_sync(~0u, p2, 4);
      p3 += __shfl_xor_sync(~0u, p3, 1); p3 += __shfl_xor_sync(~0u, p3, 2); p3 += __shfl_xor_sync(~0u, p3, 4);
      if ((tid & 7) == 0) {
        float4 y = s.ys4[hC];
        float4 g; g.x = p0; g.y = p1; g.z = p2; g.w = p3;
        s.g04[hC] = g;
        float4 yp; yp.x = y.x + p0; yp.y = y.y + p1; yp.z = y.z + p2; yp.w = y.w + p3;
        s.yp4[hC] = yp;
      }
    }
    __syncthreads();

    // ================= phase D: c-net L0 at y' + drift final =============
    if (tid < 128) {
      float bi = fmaf(s.cW0t[0][tid], tcur, s.cb0[tid]);
      float4 r = dense4(&s.cW0t[1], tid, s.yp4, 0, kH, bi);
      float4 h; h.x = lipswish(r.x); h.y = lipswish(r.y);
      h.z = lipswish(r.z); h.w = lipswish(r.w);
      s.h0c4[tid] = h;
    } else if (tid >= 256 && tid < 320) {
      // drift final layer: one h for all 4 samples, streamed vW2t from L2
      float bias = s.vb2[hDr];
      u64 a01 = pack2(bias, bias), a23 = a01;
      u64 b01 = pack2(0.f, 0.f), b23 = b01;
#pragma unroll 8
      for (int k = 0; k < kW; k += 2) {
        float wa = __ldg(&g_vW2t[k * kH + hDr]);
        ulonglong2 xa = *reinterpret_cast<const ulonglong2*>(&s.h1v4[k]);
        u64 wa2 = pack2(wa, wa);
        a01 = fma2(wa2, xa.x, a01);
        a23 = fma2(wa2, xa.y, a23);
        float wb = __ldg(&g_vW2t[(k + 1) * kH + hDr]);
        ulonglong2 xb = *reinterpret_cast<const ulonglong2*>(&s.h1v4[k + 1]);
        u64 wb2 = pack2(wb, wb);
        b01 = fma2(wb2, xb.x, b01);
        b23 = fma2(wb2, xb.y, b23);
      }
      a01 = add2(a01, b01);
      a23 = add2(a23, b23);
      float r0, r1, r2, r3;
      unpack2(a01, r0, r1); unpack2(a23, r2, r3);
      float vs = s.vscl[hDr] * dt;
      float4 f; f.x = vs * tanhf(r0); f.y = vs * tanhf(r1);
      f.z = vs * tanhf(r2); f.w = vs * tanhf(r3);
      s.f04[hDr] = f;
    }
    __syncthreads();

    // ================= phase E: c-net L1 at y' ===========================
    if (tid < 128) {
      float4 r = dense4(s.cW1t, tid, s.h0c4, 0, kW, s.cb1[tid]);
      float4 h; h.x = lipswish(r.x); h.y = lipswish(r.y);
      h.z = lipswish(r.z); h.w = lipswish(r.w);
      s.h1c4[tid] = h;
    }
    __syncthreads();

    // ================= phase F: diffusion eval 2 + Heun update ===========
    {
      u64 bias2 = *reinterpret_cast<const u64*>(&s.cb2[j0]);
      u64 A0 = bias2, A1 = bias2, A2 = bias2, A3 = bias2;
#pragma unroll 8
      for (int k = 0; k < kW; ++k) {
        u64 w2 = wrowC[(size_t)k * (kCO / 2)];
        float4 x = s.h1c4[k];
        A0 = fma2(w2, pack2(x.x, x.x), A0);
        A1 = fma2(w2, pack2(x.y, x.y), A1);
        A2 = fma2(w2, pack2(x.z, x.z), A2);
        A3 = fma2(w2, pack2(x.w, x.w), A3);
      }
      float csx = s.cscl[j0], csy = s.cscl[j0 + 1];
      int n0 = j0 & (kNoise - 1);
      float2 d0 = *reinterpret_cast<const float2*>(&s.dws[0][n0]);
      float2 d1 = *reinterpret_cast<const float2*>(&s.dws[1][n0]);
      float2 d2 = *reinterpret_cast<const float2*>(&s.dws[2][n0]);
      float2 d3 = *reinterpret_cast<const float2*>(&s.dws[3][n0]);
      float lo, hi;
      unpack2(A0, lo, hi); float p0 = tanhf(lo) * csx * d0.x + tanhf(hi) * csy * d0.y;
      unpack2(A1, lo, hi); float p1 = tanhf(lo) * csx * d1.x + tanhf(hi) * csy * d1.y;
      unpack2(A2, lo, hi); float p2 = tanhf(lo) * csx * d2.x + tanhf(hi) * csy * d2.y;
      unpack2(A3, lo, hi); float p3 = tanhf(lo) * csx * d3.x + tanhf(hi) * csy * d3.y;
      p0 += __shfl_xor_sync(~0u, p0, 1); p0 += __shfl_xor_sync(~0u, p0, 2); p0 += __shfl_xor_sync(~0u, p0, 4);
      p1 += __shfl_xor_sync(~0u, p1, 1); p1 += __shfl_xor_sync(~0u, p1, 2); p1 += __shfl_xor_sync(~0u, p1, 4);
      p2 += __shfl_xor_sync(~0u, p2, 1); p2 += __shfl_xor_sync(~0u, p2, 2); p2 += __shfl_xor_sync(~0u, p2, 4);
      p3 += __shfl_xor_sync(~0u, p3, 1); p3 += __shfl_xor_sync(~0u, p3, 2); p3 += __shfl_xor_sync(~0u, p3, 4);
      if ((tid & 7) == 0) {
        float4 y = s.ys4[hC];
        float4 f = s.f04[hC];
        float4 g = s.g04[hC];
        y.x += f.x + 0.5f * (g.x + p0);
        y.y += f.y + 0.5f * (g.y + p1);
        y.z += f.z + 0.5f * (g.z + p2);
        y.w += f.w + 0.5f * (g.w + p3);
        s.ys4[hC] = y;
      }
    }
    __syncthreads();
  }

  // final readout (index kSteps)
  if (tid < 32) {
    int b = tid >> 3, d = tid & 7;
    float acc = s.rob[d];
#pragma unroll
    for (int h = 0; h < kH; ++h)
      acc = fmaf(reinterpret_cast<const float*>(&s.ys4[h])[b], s.roWt[h][d], acc);
    out[((size_t)(bbase + b) * kT + kSteps) * kData + d] = acc;
  }
}

extern "C" void kernel_launch(void* const* d_in, const int* in_sizes, int n_in,
                              void* d_out, int out_size) {
  (void)in_sizes; (void)n_in; (void)out_size;
  const float* ts     = (const float*)d_in[0];
  const float* z0     = (const float*)d_in[1];
  const float* dW     = (const float*)d_in[2];
  const float* iW0    = (const float*)d_in[3];
  const float* ib0    = (const float*)d_in[4];
  const float* iW1    = (const float*)d_in[5];
  const float* ib1    = (const float*)d_in[6];
  const float* iW2    = (const float*)d_in[7];
  const float* ib2    = (const float*)d_in[8];
  const float* vW0    = (const float*)d_in[9];
  const float* vb0    = (const float*)d_in[10];
  const float* vW1    = (const float*)d_in[11];
  const float* vb1    = (const float*)d_in[12];
  const float* vW2    = (const float*)d_in[13];
  const float* vb2    = (const float*)d_in[14];
  const float* vscale = (const float*)d_in[15];
  const float* cW0    = (const float*)d_in[16];
  const float* cb0    = (const float*)d_in[17];
  const float* cW1    = (const float*)d_in[18];
  const float* cb1    = (const float*)d_in[19];
  const float* cW2    = (const float*)d_in[20];
  const float* cb2    = (const float*)d_in[21];
  const float* cscale = (const float*)d_in[22];
  const float* roW    = (const float*)d_in[23];
  const float* rob    = (const float*)d_in[24];

  cudaFuncSetAttribute(sde_kernel, cudaFuncAttributeMaxDynamicSharedMemorySize,
                       (int)sizeof(Smem));

  transpose_kernel<<<148, 256>>>(cW2, vW2);
  sde_kernel<<<NCTA, NTHR, sizeof(Smem)>>>(
      ts, z0, dW, iW0, ib0, iW1, ib1, iW2, ib2,
      vW0, vb0, vW1, vb1, vb2, vscale,
      cW0, cb0, cW1, cb1, cb2, cscale, roW, rob,
      (float*)d_out);
}

// round 7
// speedup vs baseline: 1.8903x; 1.0048x over previous
#include <cuda_runtime.h>
#include <math.h>

// ---------------------------------------------------------------------------
// NeuralSDE (Euler-Heun / Stratonovich) persistent kernel, round 6.
// Base = round-5 (17.4ms). Changes:
//  - diffusion final layer: accumulators paired over SAMPLES (activation u64
//    pairs come free from smem float4), only weights splat (2 MOVs vs 4).
//  - phases D/E widened to 256 threads (sample-pair split) for latency hiding.
// ---------------------------------------------------------------------------

#define kH     64
#define kNoise 16
#define kData  8
#define kW     128
#define kB     512
#define kT     1025
#define kSteps 1024
#define BS     4
#define NCTA   128
#define NTHR   512
#define kCO    1024

using u64 = unsigned long long;

// Transposed big weights (k-major). 8B-aligned for packed loads.
__device__ u64   g_cW2t[kW * kCO / 2];   // float (k,j) at k*1024 + j
__device__ float g_vW2t[kW * kH];        // float (k,h) at k*64 + h

struct Smem {
  float vW0t[65][kW];
  float cW0t[65][kW];
  float vW1t[kW][kW];
  float cW1t[kW][kW];
  float vb0[kW], vb1[kW], cb0[kW], cb1[kW];
  float vb2[kH], vscl[kH];
  float cb2[kCO];
  float cscl[kCO];
  float roWt[kH][kData];
  float rob[kData];
  // activations: float4 over the 4 samples
  float4 ys4[kH];
  float4 g04[kH];
  float4 f04[kH];
  float4 yp4[kH];
  float4 h0v4[kW];
  float4 h0c4[kW];
  float4 h1v4[kW];
  float4 h1c4[kW];
  float  dws[BS][kNoise];
};

__global__ void transpose_kernel(const float* __restrict__ cW2,
                                 const float* __restrict__ vW2) {
  int idx = blockIdx.x * blockDim.x + threadIdx.x;
  int stride = gridDim.x * blockDim.x;
  float* ct = reinterpret_cast<float*>(g_cW2t);
  for (int i = idx; i < kW * kCO; i += stride) {
    int k = i >> 10, j = i & (kCO - 1);
    ct[i] = cW2[j * kW + k];            // cW2 is (1024, 128) row-major
  }
  for (int i = idx; i < kW * kH; i += stride) {
    int k = i >> 6, h = i & (kH - 1);
    g_vW2t[i] = vW2[h * kW + k];        // vW2 is (64, 128) row-major
  }
}

__device__ __forceinline__ u64 pack2(float lo, float hi) {
  u64 r; asm("mov.b64 %0,{%1,%2};" : "=l"(r) : "f"(lo), "f"(hi)); return r;
}
__device__ __forceinline__ void unpack2(u64 v, float& lo, float& hi) {
  asm("mov.b64 {%0,%1},%2;" : "=f"(lo), "=f"(hi) : "l"(v));
}
__device__ __forceinline__ u64 fma2(u64 a, u64 b, u64 c) {
  u64 d; asm("fma.rn.f32x2 %0,%1,%2,%3;" : "=l"(d) : "l"(a), "l"(b), "l"(c));
  return d;
}
__device__ __forceinline__ u64 add2(u64 a, u64 b) {
  u64 d; asm("add.rn.f32x2 %0,%1,%2;" : "=l"(d) : "l"(a), "l"(b));
  return d;
}

__device__ __forceinline__ float lipswish(float x) {
  return 0.909f * x * (1.0f / (1.0f + expf(-x)));
}

// One (net,j) output for all 4 samples (used in phases A/B; 256 threads).
__device__ __forceinline__ float4 dense4(const float (*Wt)[kW], int j,
                                         const float4* __restrict__ x4,
                                         int k0, int n, float bias0) {
  u64 a01 = pack2(bias0, bias0), a23 = a01;
  u64 b01 = pack2(0.f, 0.f), b23 = b01;
#pragma unroll 4
  for (int k = k0; k < k0 + n; k += 2) {
    float wa = Wt[k][j];
    ulonglong2 xa = *reinterpret_cast<const ulonglong2*>(&x4[k - k0]);
    u64 wa2 = pack2(wa, wa);
    a01 = fma2(wa2, xa.x, a01);
    a23 = fma2(wa2, xa.y, a23);
    float wb = Wt[k + 1][j];
    ulonglong2 xb = *reinterpret_cast<const ulonglong2*>(&x4[k + 1 - k0]);
    u64 wb2 = pack2(wb, wb);
    b01 = fma2(wb2, xb.x, b01);
    b23 = fma2(wb2, xb.y, b23);
  }
  a01 = add2(a01, b01);
  a23 = add2(a23, b23);
  float4 r;
  unpack2(a01, r.x, r.y);
  unpack2(a23, r.z, r.w);
  return r;
}

// One (net,j) output for 2 samples (pr half); used in phases D/E (256 thr).
__device__ __forceinline__ float2 dense2(const float (*Wt)[kW], int j, int pr,
                                         const float4* __restrict__ x4,
                                         int n, float bias0) {
  u64 a = pack2(bias0, bias0);
  u64 b = pack2(0.f, 0.f);
#pragma unroll 8
  for (int k = 0; k < n; k += 2) {
    float wa = Wt[k][j];
    u64 xa = *reinterpret_cast<const u64*>(
        reinterpret_cast<const float*>(&x4[k]) + 2 * pr);
    a = fma2(pack2(wa, wa), xa, a);
    float wb = Wt[k + 1][j];
    u64 xb = *reinterpret_cast<const u64*>(
        reinterpret_cast<const float*>(&x4[k + 1]) + 2 * pr);
    b = fma2(pack2(wb, wb), xb, b);
  }
  a = add2(a, b);
  float2 r;
  unpack2(a, r.x, r.y);
  return r;
}

__global__ __launch_bounds__(NTHR, 1) void sde_kernel(
    const float* __restrict__ ts, const float* __restrict__ z0,
    const float* __restrict__ dW,
    const float* __restrict__ iW0, const float* __restrict__ ib0,
    const float* __restrict__ iW1, const float* __restrict__ ib1,
    const float* __restrict__ iW2, const float* __restrict__ ib2,
    const float* __restrict__ vW0, const float* __restrict__ vb0,
    const float* __restrict__ vW1, const float* __restrict__ vb1,
    const float* __restrict__ vb2, const float* __restrict__ vscale,
    const float* __restrict__ cW0, const float* __restrict__ cb0,
    const float* __restrict__ cW1, const float* __restrict__ cb1,
    const float* __restrict__ cb2, const float* __restrict__ cscale,
    const float* __restrict__ roW, const float* __restrict__ rob,
    float* __restrict__ out) {
  extern __shared__ char smem_raw[];
  Smem& s = *reinterpret_cast<Smem*>(smem_raw);
  const int tid = threadIdx.x;
  const int bbase = blockIdx.x * BS;

  // ---- load small weights transposed into smem ----
  for (int i = tid; i < 65 * kW; i += NTHR) {
    int k = i >> 7, j = i & 127;
    s.vW0t[k][j] = vW0[j * 65 + k];
    s.cW0t[k][j] = cW0[j * 65 + k];
  }
  for (int i = tid; i < kW * kW; i += NTHR) {
    int k = i >> 7, j = i & 127;
    s.vW1t[k][j] = vW1[j * kW + k];
    s.cW1t[k][j] = cW1[j * kW + k];
  }
  for (int i = tid; i < kW; i += NTHR) {
    s.vb0[i] = vb0[i]; s.vb1[i] = vb1[i];
    s.cb0[i] = cb0[i]; s.cb1[i] = cb1[i];
  }
  for (int i = tid; i < kH; i += NTHR) { s.vb2[i] = vb2[i]; s.vscl[i] = vscale[i]; }
  for (int i = tid; i < kCO; i += NTHR) { s.cb2[i] = cb2[i]; s.cscl[i] = cscale[i]; }
  for (int i = tid; i < kH * kData; i += NTHR) {
    int h = i >> 3, d = i & 7;
    s.roWt[h][d] = roW[d * kH + h];
  }
  if (tid < kData) s.rob[tid] = rob[tid];
  __syncthreads();

  const float dt = __ldg(&ts[1]) - __ldg(&ts[0]);
  const float sqdt = sqrtf(dt);

  // ---- initial MLP: z0 (8) -> relu 128 -> relu 128 -> 64 ----
  if (tid < 256) {
    int j = tid & 127, pr = tid >> 7;  // samples 2pr, 2pr+1
    float a0 = __ldg(&ib0[j]), a1 = a0;
#pragma unroll
    for (int k = 0; k < 8; ++k) {
      float w = __ldg(&iW0[j * 8 + k]);
      a0 = fmaf(w, __ldg(&z0[(bbase + 2 * pr) * 8 + k]), a0);
      a1 = fmaf(w, __ldg(&z0[(bbase + 2 * pr + 1) * 8 + k]), a1);
    }
    float* d0 = reinterpret_cast<float*>(&s.h0v4[j]) + 2 * pr;
    d0[0] = fmaxf(a0, 0.f); d0[1] = fmaxf(a1, 0.f);
  }
  __syncthreads();
  if (tid < 256) {
    int j = tid & 127, pr = tid >> 7;
    float a0 = __ldg(&ib1[j]), a1 = a0;
#pragma unroll 4
    for (int k = 0; k < kW; ++k) {
      float w = __ldg(&iW1[j * kW + k]);
      const float* x = reinterpret_cast<const float*>(&s.h0v4[k]) + 2 * pr;
      a0 = fmaf(w, x[0], a0);
      a1 = fmaf(w, x[1], a1);
    }
    float* d0 = reinterpret_cast<float*>(&s.h0c4[j]) + 2 * pr;  // temp
    d0[0] = fmaxf(a0, 0.f); d0[1] = fmaxf(a1, 0.f);
  }
  __syncthreads();
  if (tid < 256) {
    int b = tid >> 6, h = tid & 63;
    float acc = __ldg(&ib2[h]);
#pragma unroll 4
    for (int k = 0; k < kW; ++k)
      acc = fmaf(reinterpret_cast<const float*>(&s.h0c4[k])[b],
                 __ldg(&iW2[h * kW + k]), acc);
    reinterpret_cast<float*>(&s.ys4[h])[b] = acc;
  }
  __syncthreads();

  // precomputed per-thread constants
  const int jA = tid & 127;             // phases A/B: (net, j), 4 samples
  const int netA = tid >> 7;            // valid for tid < 256
  const int prDE = tid >> 7;            // phases D/E sample pair (tid < 256)
  const int j0 = tid << 1;              // diffusion col pair (phases C/F)
  const int hC = tid >> 3;              // diffusion h
  const u64* wrowC = g_cW2t + tid;      // row k at + k*512 (u64 units)
  const int hDr = tid - 256;            // drift h (tid in [256,320))

  for (int st = 0; st < kSteps; ++st) {
    const float tcur = __ldg(&ts[st]);

    // ================= phase A: dense L0 of both nets + extras ===========
    if (tid < 256) {
      const float (*W0)[kW] = netA ? s.cW0t : s.vW0t;
      const float* bb = netA ? s.cb0 : s.vb0;
      float bi = fmaf(W0[0][jA], tcur, bb[jA]);
      float4 r = dense4(&W0[1], jA, s.ys4, 0, kH, bi);
      float4 h; h.x = lipswish(r.x); h.y = lipswish(r.y);
      h.z = lipswish(r.z); h.w = lipswish(r.w);
      (netA ? s.h0c4 : s.h0v4)[jA] = h;
    } else if (tid >= 448) {
      int i = tid - 448;                 // 64 tasks: dW load
      int b = i >> 4, n = i & 15;
      s.dws[b][n] = __ldg(&dW[((size_t)st * kB + bbase + b) * kNoise + n]) * sqdt;
    } else if (tid >= 416) {
      int i = tid - 416;                 // 32 tasks: readout of y_st
      int b = i >> 3, d = i & 7;
      float acc = s.rob[d];
#pragma unroll
      for (int h = 0; h < kH; ++h)
        acc = fmaf(reinterpret_cast<const float*>(&s.ys4[h])[b], s.roWt[h][d], acc);
      out[((size_t)(bbase + b) * kT + st) * kData + d] = acc;
    }
    __syncthreads();

    // ================= phase B: dense L1 of both nets ====================
    if (tid < 256) {
      const float (*W1)[kW] = netA ? s.cW1t : s.vW1t;
      const float* bb = netA ? s.cb1 : s.vb1;
      const float4* src = netA ? s.h0c4 : s.h0v4;
      float4 r = dense4(W1, jA, src, 0, kW, bb[jA]);
      float4 h; h.x = lipswish(r.x); h.y = lipswish(r.y);
      h.z = lipswish(r.z); h.w = lipswish(r.w);
      (netA ? s.h1c4 : s.h1v4)[jA] = h;
    }
    __syncthreads();

    // ================= phase C: diffusion eval 1 (all threads) ===========
    {
      const float2 cb = *reinterpret_cast<const float2*>(&s.cb2[j0]);
      u64 A00 = pack2(cb.x, cb.x), A01 = A00;   // col j0: samples(0,1),(2,3)
      u64 A10 = pack2(cb.y, cb.y), A11 = A10;   // col j0+1
#pragma unroll 8
      for (int k = 0; k < kW; ++k) {
        u64 w2 = wrowC[(size_t)k * (kCO / 2)];
        float wlo, whi; unpack2(w2, wlo, whi);
        u64 w00 = pack2(wlo, wlo);
        u64 w11 = pack2(whi, whi);
        ulonglong2 x = *reinterpret_cast<const ulonglong2*>(&s.h1c4[k]);
        A00 = fma2(w00, x.x, A00);
        A01 = fma2(w00, x.y, A01);
        A10 = fma2(w11, x.x, A10);
        A11 = fma2(w11, x.y, A11);
      }
      float csx = s.cscl[j0], csy = s.cscl[j0 + 1];
      int n0 = j0 & (kNoise - 1);
      float2 d0 = *reinterpret_cast<const float2*>(&s.dws[0][n0]);
      float2 d1 = *reinterpret_cast<const float2*>(&s.dws[1][n0]);
      float2 d2 = *reinterpret_cast<const float2*>(&s.dws[2][n0]);
      float2 d3 = *reinterpret_cast<const float2*>(&s.dws[3][n0]);
      float s0j0, s1j0, s2j0, s3j0, s0j1, s1j1, s2j1, s3j1;
      unpack2(A00, s0j0, s1j0); unpack2(A01, s2j0, s3j0);
      unpack2(A10, s0j1, s1j1); unpack2(A11, s2j1, s3j1);
      float p0 = tanhf(s0j0) * csx * d0.x + tanhf(s0j1) * csy * d0.y;
      float p1 = tanhf(s1j0) * csx * d1.x + tanhf(s1j1) * csy * d1.y;
      float p2 = tanhf(s2j0) * csx * d2.x + tanhf(s2j1) * csy * d2.y;
      float p3 = tanhf(s3j0) * csx * d3.x + tanhf(s3j1) * csy * d3.y;
      p0 += __shfl_xor_sync(~0u, p0, 1); p0 += __shfl_xor_sync(~0u, p0, 2); p0 += __shfl_xor_sync(~0u, p0, 4);
      p1 += __shfl_xor_sync(~0u, p1, 1); p1 += __shfl_xor_sync(~0u, p1, 2); p1 += __shfl_xor_sync(~0u, p1, 4);
      p2 += __shfl_xor_sync(~0u, p2, 1); p2 += __shfl_xor_sync(~0u, p2, 2); p2 += __shfl_xor_sync(~0u, p2, 4);
      p3 += __shfl_xor_sync(~0u, p3, 1); p3 += __shfl_xor_sync(~0u, p3, 2); p3 += __shfl_xor_sync(~0u, p3, 4);
      if ((tid & 7) == 0) {
        float4 y = s.ys4[hC];
        float4 g; g.x = p0; g.y = p1; g.z = p2; g.w = p3;
        s.g04[hC] = g;
        float4 yp; yp.x = y.x + p0; yp.y = y.y + p1; yp.z = y.z + p2; yp.w = y.w + p3;
        s.yp4[hC] = yp;
      }
    }
    __syncthreads();

    // ================= phase D: c-net L0 at y' + drift final =============
    if (tid < 256) {
      float bi = fmaf(s.cW0t[0][jA], tcur, s.cb0[jA]);
      float2 r = dense2(&s.cW0t[1], jA, prDE, s.yp4, kH, bi);
      float2 h; h.x = lipswish(r.x); h.y = lipswish(r.y);
      *reinterpret_cast<float2*>(
          reinterpret_cast<float*>(&s.h0c4[jA]) + 2 * prDE) = h;
    } else if (tid < 320) {
      // drift final layer: one h for all 4 samples, streamed vW2t from L2
      float bias = s.vb2[hDr];
      u64 a01 = pack2(bias, bias), a23 = a01;
      u64 b01 = pack2(0.f, 0.f), b23 = b01;
#pragma unroll 8
      for (int k = 0; k < kW; k += 2) {
        float wa = __ldg(&g_vW2t[k * kH + hDr]);
        ulonglong2 xa = *reinterpret_cast<const ulonglong2*>(&s.h1v4[k]);
        u64 wa2 = pack2(wa, wa);
        a01 = fma2(wa2, xa.x, a01);
        a23 = fma2(wa2, xa.y, a23);
        float wb = __ldg(&g_vW2t[(k + 1) * kH + hDr]);
        ulonglong2 xb = *reinterpret_cast<const ulonglong2*>(&s.h1v4[k + 1]);
        u64 wb2 = pack2(wb, wb);
        b01 = fma2(wb2, xb.x, b01);
        b23 = fma2(wb2, xb.y, b23);
      }
      a01 = add2(a01, b01);
      a23 = add2(a23, b23);
      float r0, r1, r2, r3;
      unpack2(a01, r0, r1); unpack2(a23, r2, r3);
      float vs = s.vscl[hDr] * dt;
      float4 f; f.x = vs * tanhf(r0); f.y = vs * tanhf(r1);
      f.z = vs * tanhf(r2); f.w = vs * tanhf(r3);
      s.f04[hDr] = f;
    }
    __syncthreads();

    // ================= phase E: c-net L1 at y' ===========================
    if (tid < 256) {
      float2 r = dense2(s.cW1t, jA, prDE, s.h0c4, kW, s.cb1[jA]);
      float2 h; h.x = lipswish(r.x); h.y = lipswish(r.y);
      *reinterpret_cast<float2*>(
          reinterpret_cast<float*>(&s.h1c4[jA]) + 2 * prDE) = h;
    }
    __syncthreads();

    // ================= phase F: diffusion eval 2 + Heun update ===========
    {
      const float2 cb = *reinterpret_cast<const float2*>(&s.cb2[j0]);
      u64 A00 = pack2(cb.x, cb.x), A01 = A00;
      u64 A10 = pack2(cb.y, cb.y), A11 = A10;
#pragma unroll 8
      for (int k = 0; k < kW; ++k) {
        u64 w2 = wrowC[(size_t)k * (kCO / 2)];
        float wlo, whi; unpack2(w2, wlo, whi);
        u64 w00 = pack2(wlo, wlo);
        u64 w11 = pack2(whi, whi);
        ulonglong2 x = *reinterpret_cast<const ulonglong2*>(&s.h1c4[k]);
        A00 = fma2(w00, x.x, A00);
        A01 = fma2(w00, x.y, A01);
        A10 = fma2(w11, x.x, A10);
        A11 = fma2(w11, x.y, A11);
      }
      float csx = s.cscl[j0], csy = s.cscl[j0 + 1];
      int n0 = j0 & (kNoise - 1);
      float2 d0 = *reinterpret_cast<const float2*>(&s.dws[0][n0]);
      float2 d1 = *reinterpret_cast<const float2*>(&s.dws[1][n0]);
      float2 d2 = *reinterpret_cast<const float2*>(&s.dws[2][n0]);
      float2 d3 = *reinterpret_cast<const float2*>(&s.dws[3][n0]);
      float s0j0, s1j0, s2j0, s3j0, s0j1, s1j1, s2j1, s3j1;
      unpack2(A00, s0j0, s1j0); unpack2(A01, s2j0, s3j0);
      unpack2(A10, s0j1, s1j1); unpack2(A11, s2j1, s3j1);
      float p0 = tanhf(s0j0) * csx * d0.x + tanhf(s0j1) * csy * d0.y;
      float p1 = tanhf(s1j0) * csx * d1.x + tanhf(s1j1) * csy * d1.y;
      float p2 = tanhf(s2j0) * csx * d2.x + tanhf(s2j1) * csy * d2.y;
      float p3 = tanhf(s3j0) * csx * d3.x + tanhf(s3j1) * csy * d3.y;
      p0 += __shfl_xor_sync(~0u, p0, 1); p0 += __shfl_xor_sync(~0u, p0, 2); p0 += __shfl_xor_sync(~0u, p0, 4);
      p1 += __shfl_xor_sync(~0u, p1, 1); p1 += __shfl_xor_sync(~0u, p1, 2); p1 += __shfl_xor_sync(~0u, p1, 4);
      p2 += __shfl_xor_sync(~0u, p2, 1); p2 += __shfl_xor_sync(~0u, p2, 2); p2 += __shfl_xor_sync(~0u, p2, 4);
      p3 += __shfl_xor_sync(~0u, p3, 1); p3 += __shfl_xor_sync(~0u, p3, 2); p3 += __shfl_xor_sync(~0u, p3, 4);
      if ((tid & 7) == 0) {
        float4 y = s.ys4[hC];
        float4 f = s.f04[hC];
        float4 g = s.g04[hC];
        y.x += f.x + 0.5f * (g.x + p0);
        y.y += f.y + 0.5f * (g.y + p1);
        y.z += f.z + 0.5f * (g.z + p2);
        y.w += f.w + 0.5f * (g.w + p3);
        s.ys4[hC] = y;
      }
    }
    __syncthreads();
  }

  // final readout (index kSteps)
  if (tid < 32) {
    int b = tid >> 3, d = tid & 7;
    float acc = s.rob[d];
#pragma unroll
    for (int h = 0; h < kH; ++h)
      acc = fmaf(reinterpret_cast<const float*>(&s.ys4[h])[b], s.roWt[h][d], acc);
    out[((size_t)(bbase + b) * kT + kSteps) * kData + d] = acc;
  }
}

extern "C" void kernel_launch(void* const* d_in, const int* in_sizes, int n_in,
                              void* d_out, int out_size) {
  (void)in_sizes; (void)n_in; (void)out_size;
  const float* ts     = (const float*)d_in[0];
  const float* z0     = (const float*)d_in[1];
  const float* dW     = (const float*)d_in[2];
  const float* iW0    = (const float*)d_in[3];
  const float* ib0    = (const float*)d_in[4];
  const float* iW1    = (const float*)d_in[5];
  const float* ib1    = (const float*)d_in[6];
  const float* iW2    = (const float*)d_in[7];
  const float* ib2    = (const float*)d_in[8];
  const float* vW0    = (const float*)d_in[9];
  const float* vb0    = (const float*)d_in[10];
  const float* vW1    = (const float*)d_in[11];
  const float* vb1    = (const float*)d_in[12];
  const float* vW2    = (const float*)d_in[13];
  const float* vb2    = (const float*)d_in[14];
  const float* vscale = (const float*)d_in[15];
  const float* cW0    = (const float*)d_in[16];
  const float* cb0    = (const float*)d_in[17];
  const float* cW1    = (const float*)d_in[18];
  const float* cb1    = (const float*)d_in[19];
  const float* cW2    = (const float*)d_in[20];
  const float* cb2    = (const float*)d_in[21];
  const float* cscale = (const float*)d_in[22];
  const float* roW    = (const float*)d_in[23];
  const float* rob    = (const float*)d_in[24];

  cudaFuncSetAttribute(sde_kernel, cudaFuncAttributeMaxDynamicSharedMemorySize,
                       (int)sizeof(Smem));

  transpose_kernel<<<148, 256>>>(cW2, vW2);
  sde_kernel<<<NCTA, NTHR, sizeof(Smem)>>>(
      ts, z0, dW, iW0, ib0, iW1, ib1, iW2, ib2,
      vW0, vb0, vW1, vb1, vb2, vscale,
      cW0, cb0, cW1, cb1, cb2, cscale, roW, rob,
      (float*)d_out);
}